// round 1
// baseline (speedup 1.0000x reference)
#include <cuda_runtime.h>
#include <math.h>

#define HW_   96
#define CIN_  64
#define COUT_ 64
#define B_    4
#define T_    8
#define PLANE (HW_*HW_)
#define TILE  32
#define COB   16      // output channels per block
#define CICH  8       // input-channel chunk in smem
#define HALO  34
#define SPITCH 35     // padded smem row stride
#define NTHR  128

// Scratch state (no runtime allocation allowed)
__device__ float g_h [B_*COUT_*PLANE];
__device__ float g_rh[B_*COUT_*PLANE];
__device__ float g_z [B_*COUT_*PLANE];

typedef unsigned long long u64;

__device__ __forceinline__ u64 pack2(float lo, float hi) {
    u64 r; asm("mov.b64 %0, {%1, %2};" : "=l"(r) : "f"(lo), "f"(hi)); return r;
}
__device__ __forceinline__ void unpack2(u64 v, float &lo, float &hi) {
    asm("mov.b64 {%0, %1}, %2;" : "=f"(lo), "=f"(hi) : "l"(v));
}
// packed fp32x2 FMA: d = a*b + d   (Blackwell FFMA2)
__device__ __forceinline__ void fma2(u64 &d, u64 a, u64 b) {
    asm("fma.rn.f32x2 %0, %1, %2, %0;" : "+l"(d) : "l"(a), "l"(b));
}

// Computes a 32x32 output tile of a 3x3 SAME conv over concat([srcA(64ch), srcB(64ch)])
// for 16 output channels [co_base, co_base+16). acc holds packed pixel-pairs.
__device__ __forceinline__ void conv_tile(
    const float* __restrict__ srcA,   // [64][96][96] for this (b,t)
    const float* __restrict__ srcB,   // [64][96][96] for this b (h or r*h)
    const float* __restrict__ wts,    // [64][128][3][3]
    const float* __restrict__ bias,   // [64]
    int co_base, int tile_x, int tile_y, int tid,
    u64 acc[4][COB])
{
    __shared__ float  s_in[CICH][HALO][SPITCH];
    __shared__ float2 s_w [CICH][9][COB];

    const int tx = tid & 15;     // 0..15  (x pixel-pair)
    const int ty = tid >> 4;     // 0..7   (4-row group)

    #pragma unroll
    for (int co = 0; co < COB; co++) {
        float bv = bias[co_base + co];
        u64 bp = pack2(bv, bv);
        #pragma unroll
        for (int pr = 0; pr < 4; pr++) acc[pr][co] = bp;
    }

    const int base_y = tile_y * TILE - 1;
    const int base_x = tile_x * TILE - 1;
    const int lx = tx * 2;
    const int ly = ty * 4;

    for (int src = 0; src < 2; src++) {
        const float* sp = src ? srcB : srcA;
        for (int cc = 0; cc < CIN_ / CICH; cc++) {
            // ---- fill input tile (with halo, zero-padded) ----
            for (int i = tid; i < CICH * HALO * HALO; i += NTHR) {
                int ci  = i / (HALO * HALO);
                int rem = i - ci * (HALO * HALO);
                int r = rem / HALO;
                int c = rem - r * HALO;
                int gy = base_y + r, gx = base_x + c;
                float v = 0.0f;
                if ((unsigned)gy < HW_ && (unsigned)gx < HW_)
                    v = sp[(size_t)(cc * CICH + ci) * PLANE + gy * HW_ + gx];
                s_in[ci][r][c] = v;
            }
            // ---- fill weights, duplicated into both packed halves ----
            for (int i = tid; i < CICH * 9 * COB; i += NTHR) {
                int co = i & (COB - 1);
                int k  = (i >> 4) % 9;
                int ci = i / (9 * COB);
                float wv = wts[((size_t)(co_base + co) * 128 + src * 64 + cc * CICH + ci) * 9 + k];
                s_w[ci][k][co] = make_float2(wv, wv);
            }
            __syncthreads();

            #pragma unroll 1
            for (int ci = 0; ci < CICH; ci++) {
                // 6 rows x 4 cols of input around this thread's 4x2 pixel patch
                float a[6][4];
                #pragma unroll
                for (int r = 0; r < 6; r++)
                    #pragma unroll
                    for (int c = 0; c < 4; c++)
                        a[r][c] = s_in[ci][ly + r][lx + c];
                u64 p[6][3];
                #pragma unroll
                for (int r = 0; r < 6; r++)
                    #pragma unroll
                    for (int kx = 0; kx < 3; kx++)
                        p[r][kx] = pack2(a[r][kx], a[r][kx + 1]);

                #pragma unroll
                for (int co = 0; co < COB; co++) {
                    u64 wv[9];
                    #pragma unroll
                    for (int k = 0; k < 9; k++)
                        wv[k] = *reinterpret_cast<const u64*>(&s_w[ci][k][co]);
                    #pragma unroll
                    for (int pr = 0; pr < 4; pr++)
                        #pragma unroll
                        for (int ky = 0; ky < 3; ky++)
                            #pragma unroll
                            for (int kx = 0; kx < 3; kx++)
                                fma2(acc[pr][co], wv[ky * 3 + kx], p[pr + ky][kx]);
                }
            }
            __syncthreads();
        }
    }
}

__device__ __forceinline__ float sigmoidf_(float v) {
    return 1.0f / (1.0f + expf(-v));
}

// grid: (3, 3, B*2*4)  z: b = bz>>3, gate = (bz>>2)&1, cg = bz&3
__global__ void __launch_bounds__(NTHR) gates_kernel(
    const float* __restrict__ x,
    const float* __restrict__ w_r, const float* __restrict__ b_r,
    const float* __restrict__ w_z, const float* __restrict__ b_z,
    int t)
{
    const int bz   = blockIdx.z;
    const int b    = bz >> 3;
    const int gate = (bz >> 2) & 1;
    const int cg   = bz & 3;

    const float* srcA = x + (size_t)(b * T_ + t) * CIN_ * PLANE;
    const float* srcB = g_h + (size_t)b * COUT_ * PLANE;
    const float* wts  = gate ? w_z : w_r;
    const float* bias = gate ? b_z : b_r;

    u64 acc[4][COB];
    const int tid = threadIdx.x;
    conv_tile(srcA, srcB, wts, bias, cg * COB, blockIdx.x, blockIdx.y, tid, acc);

    const int tx = tid & 15, ty = tid >> 4;
    const int gy0 = blockIdx.y * TILE + ty * 4;
    const int gx  = blockIdx.x * TILE + tx * 2;
    #pragma unroll
    for (int pr = 0; pr < 4; pr++) {
        int gy = gy0 + pr;
        #pragma unroll
        for (int co = 0; co < COB; co++) {
            float v0, v1; unpack2(acc[pr][co], v0, v1);
            int cglob = cg * COB + co;
            size_t idx = (size_t)(b * COUT_ + cglob) * PLANE + gy * HW_ + gx;
            float s0 = sigmoidf_(v0);
            float s1 = sigmoidf_(v1);
            if (gate == 0) {
                g_rh[idx]     = s0 * g_h[idx];
                g_rh[idx + 1] = s1 * g_h[idx + 1];
            } else {
                g_z[idx]     = s0;
                g_z[idx + 1] = s1;
            }
        }
    }
}

// grid: (3, 3, B*4)  z: b = bz>>2, cg = bz&3
__global__ void __launch_bounds__(NTHR) update_kernel(
    const float* __restrict__ x,
    const float* __restrict__ w_h, const float* __restrict__ b_h,
    float* __restrict__ out, int t)
{
    const int bz = blockIdx.z;
    const int b  = bz >> 2;
    const int cg = bz & 3;

    const float* srcA = x + (size_t)(b * T_ + t) * CIN_ * PLANE;
    const float* srcB = g_rh + (size_t)b * COUT_ * PLANE;

    u64 acc[4][COB];
    const int tid = threadIdx.x;
    conv_tile(srcA, srcB, w_h, b_h, cg * COB, blockIdx.x, blockIdx.y, tid, acc);

    const int tx = tid & 15, ty = tid >> 4;
    const int gy0 = blockIdx.y * TILE + ty * 4;
    const int gx  = blockIdx.x * TILE + tx * 2;
    #pragma unroll
    for (int pr = 0; pr < 4; pr++) {
        int gy = gy0 + pr;
        #pragma unroll
        for (int co = 0; co < COB; co++) {
            float v0, v1; unpack2(acc[pr][co], v0, v1);
            int cglob = cg * COB + co;
            size_t idx  = (size_t)(b * COUT_ + cglob) * PLANE + gy * HW_ + gx;
            size_t oidx = (size_t)((b * T_ + t) * COUT_ + cglob) * PLANE + gy * HW_ + gx;
            float ht0 = tanhf(v0), ht1 = tanhf(v1);
            float z0 = g_z[idx],     z1 = g_z[idx + 1];
            float h0 = g_h[idx],     h1 = g_h[idx + 1];
            float hn0 = h0 + z0 * (ht0 - h0);
            float hn1 = h1 + z1 * (ht1 - h1);
            g_h[idx]     = hn0;  g_h[idx + 1] = hn1;
            out[oidx]    = hn0;  out[oidx + 1] = hn1;
        }
    }
}

__global__ void zero_h_kernel() {
    int i = blockIdx.x * 256 + threadIdx.x;
    if (i < B_ * COUT_ * PLANE) g_h[i] = 0.0f;
}

extern "C" void kernel_launch(void* const* d_in, const int* in_sizes, int n_in,
                              void* d_out, int out_size)
{
    const float* x   = (const float*)d_in[0];
    const float* w_r = (const float*)d_in[1];
    const float* b_r = (const float*)d_in[2];
    const float* w_z = (const float*)d_in[3];
    const float* b_z = (const float*)d_in[4];
    const float* w_h = (const float*)d_in[5];
    const float* b_h = (const float*)d_in[6];
    float* out = (float*)d_out;

    zero_h_kernel<<<(B_ * COUT_ * PLANE + 255) / 256, 256>>>();

    dim3 gGrid(HW_ / TILE, HW_ / TILE, B_ * 2 * (COUT_ / COB));  // 3,3,32
    dim3 uGrid(HW_ / TILE, HW_ / TILE, B_ * (COUT_ / COB));      // 3,3,16
    for (int t = 0; t < T_; t++) {
        gates_kernel<<<gGrid, NTHR>>>(x, w_r, b_r, w_z, b_z, t);
        update_kernel<<<uGrid, NTHR>>>(x, w_h, b_h, out, t);
    }
}